// round 17
// baseline (speedup 1.0000x reference)
#include <cuda_runtime.h>
#include <cuda_fp16.h>
#include <stdint.h>

// Problem dims (fixed)
#define T_STEPS 2048
#define BATCH   256
#define INP     256
#define HID     512
#define KTOT    768

// Block = (jTile 0..31, bTile 0..3): 16 hidden cols x 64 batch rows; 128 blocks
#define JT 16
#define BT 64
#define THREADS 512            // 16 warps: kg(4) x wn(2) x wm(2) -> 32x32 tile per warp
#define KC 128                 // k elems per staged chunk
#define NCH (KTOT / KC)        // 6 chunks (0-1: x, 2-5: h)
#define NBG 32                 // blocks per barrier group (one bTile)

// SMEM strides in 32-bit words (row byte-stride % 128 == 16 -> conflict-free ldsm)
#define W_STRIDE 388           // 768 fp16 = 384 words + 4 pad
#define A_STRIDE 68            // 128 fp16 = 64 words + 4 pad
#define G_STRIDE 65
#define GT_WORDS (64 * G_STRIDE)
#define ABUF_WORDS (BT * A_STRIDE)     // 4352
#define ABUF_BYTES (ABUF_WORDS * 4)    // 17408

#define OFF_W    0
#define SZ_W     (64 * W_STRIDE * 4)           // 99,328 (single fp16 plane)
#define OFF_A    SZ_W                          // 99,328
#define OFF_GT   (OFF_A + 2 * ABUF_BYTES)      // 134,144 (4 split-K gate buffers)
#define OFF_BIAS (OFF_GT + 4 * GT_WORDS * 4)   // 200,704
#define SMEM_BYTES (OFF_BIAS + 256 + 16)       // 200,976

// Persistent state: h as packed half2 words, double-buffered; fp32 copy for decode
__device__ uint32_t g_h[2][BATCH * HID / 2];
__device__ float    g_hf[BATCH * HID];
__device__ __align__(128) volatile unsigned g_flag[4][32];   // per-group barrier lines

__device__ __forceinline__ uint32_t h2u(__half2 v) {
    return *reinterpret_cast<uint32_t*>(&v);
}
__device__ __forceinline__ float fast_sigmoid(float x) {
    x = fminf(fmaxf(x, -30.f), 30.f);
    return __fdividef(1.f, 1.f + __expf(-x));
}
__device__ __forceinline__ float fast_tanh(float x) {
    x = fminf(fmaxf(x, -15.f), 15.f);
    float e = __expf(2.f * x);
    return __fdividef(e - 1.f, e + 1.f);
}
__device__ __forceinline__ void ldsm4(uint32_t* r, uint32_t saddr) {
    asm volatile("ldmatrix.sync.aligned.m8n8.x4.shared.b16 {%0,%1,%2,%3}, [%4];"
                 : "=r"(r[0]), "=r"(r[1]), "=r"(r[2]), "=r"(r[3]) : "r"(saddr));
}
#define MMA_F16(D, A, B0, B1)                                               \
    asm volatile("mma.sync.aligned.m16n8k16.row.col.f32.f16.f16.f32 "       \
                 "{%0,%1,%2,%3}, {%4,%5,%6,%7}, {%8,%9}, {%0,%1,%2,%3};"    \
                 : "+f"((D)[0]), "+f"((D)[1]), "+f"((D)[2]), "+f"((D)[3])   \
                 : "r"((A)[0]), "r"((A)[1]), "r"((A)[2]), "r"((A)[3]),      \
                   "r"(B0), "r"(B1));

// ONE kernel: init + 2048 fused steps + decode. Grid (32, 4) x 512 threads.
__global__ __launch_bounds__(THREADS, 1)
void lstm_w16w_kernel(const float* __restrict__ x_all,
                      const float* __restrict__ h0,
                      const float* __restrict__ c0,
                      const float* __restrict__ W_ih,
                      const float* __restrict__ W_hh,
                      const float* __restrict__ b_ih,
                      const float* __restrict__ b_hh,
                      const float* __restrict__ W_dec,
                      const float* __restrict__ b_dec,
                      float* __restrict__ out)
{
    extern __shared__ __align__(16) char sm[];
    uint32_t* W      = (uint32_t*)(sm + OFF_W);
    uint32_t* Ab     = (uint32_t*)(sm + OFF_A);
    float*    gates  = (float*)   (sm + OFF_GT);    // [4][64][65]
    float*    bias_s = (float*)   (sm + OFF_BIAS);
    __shared__ unsigned s_base;

    const int tid  = threadIdx.x;
    const int lane = tid & 31, warp = tid >> 5;
    const int wm = warp & 1;          // batch half (32 rows)
    const int wn = (warp >> 1) & 1;   // 32-gatecol half
    const int kg = warp >> 2;         // K-group: 2 k16-slices per chunk each
    const int jTile = blockIdx.x;     // 0..31
    const int bTile = blockIdx.y;     // 0..3 (= barrier group)

    if (tid == 0) s_base = g_flag[bTile][jTile];   // replay-safe monotonic base

    // ---- one-time: weights -> SMEM, single fp16 plane (K-major, padded) ----
    {
        int r = tid >> 3;                          // weight row 0..63 (tt*16+jj)
        int grow = (r >> 4) * HID + jTile * JT + (r & 15);
        int kbase = (tid & 7) * 96;
        for (int i = 0; i < 48; ++i) {
            int k = kbase + 2 * i;
            float2 v = (k < INP)
                ? *(const float2*)(W_ih + (size_t)grow * INP + k)
                : *(const float2*)(W_hh + (size_t)grow * HID + (k - INP));
            W[r * W_STRIDE + k / 2] = h2u(__floats2half2_rn(v.x, v.y));
        }
        if (tid < 64) {
            int gr = (tid >> 4) * HID + jTile * JT + (tid & 15);
            bias_s[tid] = b_ih[gr] + b_hh[gr];
        }
    }

    // ---- epilogue ownership: thread owns (eb, ej0..ej0+1); c in registers ----
    const int eb  = tid >> 3;                      // 0..63
    const int ebg = bTile * BT + eb;
    const int ej0 = (tid & 7) * 2;                 // 0..14
    const int jg0 = jTile * JT + ej0;
    const int hwi = ebg * (HID / 2) + jg0 / 2;     // one half2 word per thread
    float creg[2];
    {
        float2 cv = *(const float2*)(c0 + (size_t)ebg * HID + jg0);
        creg[0] = cv.x; creg[1] = cv.y;
        float2 hv = *(const float2*)(h0 + (size_t)ebg * HID + jg0);
        g_h[0][hwi] = h2u(__floats2half2_rn(hv.x, hv.y));
    }
    __syncthreads();
    const unsigned fbase = s_base;
    unsigned seq = 0;

#define GROUP_ARRIVE()                                                      \
    do {                                                                    \
        __syncthreads();                                                    \
        ++seq;                                                              \
        if (tid == 0) { __threadfence(); g_flag[bTile][jTile] = fbase + seq; } \
    } while (0)
#define GROUP_WAIT()                                                        \
    do {                                                                    \
        if (tid < 32) {                                                     \
            while (g_flag[bTile][tid] - fbase < seq) { }                    \
            __threadfence();                                                \
        }                                                                   \
        __syncthreads();                                                    \
    } while (0)

    GROUP_ARRIVE();   // publish h init (seq = 1)

    // ---- ldmatrix lane addressing (bytes, shared space) ----
    const uint32_t a_sh = (uint32_t)__cvta_generic_to_shared(Ab);
    const uint32_t w_sh = (uint32_t)__cvta_generic_to_shared(W);
    const int rowoff = (lane & 7) + ((lane >> 3) & 1) * 8;
    const int khalf4 = (lane >> 4) * 4;
    // W: warp covers 32 gate-cols = rows wn*32 .. wn*32+31 (two 16-row ldsm)
    const uint32_t wlane0 = w_sh + ((wn * 32 + rowoff)      * W_STRIDE + khalf4) * 4;
    const uint32_t wlane1 = w_sh + ((wn * 32 + 16 + rowoff) * W_STRIDE + khalf4) * 4;
    uint32_t alane[2];
#pragma unroll
    for (int mf = 0; mf < 2; ++mf)
        alane[mf] = a_sh + ((wm * 32 + mf * 16 + rowoff) * A_STRIDE + khalf4) * 4;

    // staging: 8 threads per batch row, 16 k elems (8 half2 words) each
    const int srow = tid >> 3;
    const int sq   = tid & 7;
    const int sbrow = bTile * BT + srow;
    const int sdst  = srow * A_STRIDE + sq * 8;    // word offset in A plane

    for (int t = 0; t < T_STEPS; ++t) {
        const float* __restrict__ x_t = x_all + (size_t)t * BATCH * INP;
        const uint32_t* __restrict__ h_in = g_h[t & 1];
        uint32_t* __restrict__ h_out = g_h[(t & 1) ^ 1];

        float d[2][4][4];                          // [mf][nf][quad]
#pragma unroll
        for (int mf = 0; mf < 2; ++mf)
#pragma unroll
            for (int nf = 0; nf < 4; ++nf)
#pragma unroll
                for (int q = 0; q < 4; ++q) d[mf][nf][q] = 0.f;

        // ---- stage chunk 0 (pure x) into buf 0 ----
        {
            const float* src = x_t + (size_t)sbrow * INP + sq * 16;
            float4 f0 = *(const float4*)(src);
            float4 f1 = *(const float4*)(src + 4);
            float4 f2 = *(const float4*)(src + 8);
            float4 f3 = *(const float4*)(src + 12);
            *(uint4*)&Ab[sdst] = make_uint4(h2u(__floats2half2_rn(f0.x, f0.y)),
                                            h2u(__floats2half2_rn(f0.z, f0.w)),
                                            h2u(__floats2half2_rn(f1.x, f1.y)),
                                            h2u(__floats2half2_rn(f1.z, f1.w)));
            *(uint4*)&Ab[sdst + 4] = make_uint4(h2u(__floats2half2_rn(f2.x, f2.y)),
                                                h2u(__floats2half2_rn(f2.z, f2.w)),
                                                h2u(__floats2half2_rn(f3.x, f3.y)),
                                                h2u(__floats2half2_rn(f3.z, f3.w)));
        }
        __syncthreads();

        int buf = 0;
        for (int c = 0; c < NCH; ++c) {
            // deferred barrier wait: h first needed by chunk 1's prefetch of chunk 2
            if (c == 1) GROUP_WAIT();

            // ---- prefetch chunk c+1 ----
            uint4 pa, pb;
            bool have_next = (c < NCH - 1);
            if (have_next) {
                int cn = c + 1;
                if (cn < 2) {   // x chunk: LDG fp32 + cvt
                    const float* src = x_t + (size_t)sbrow * INP + cn * KC + sq * 16;
                    float4 f0 = *(const float4*)(src);
                    float4 f1 = *(const float4*)(src + 4);
                    float4 f2 = *(const float4*)(src + 8);
                    float4 f3 = *(const float4*)(src + 12);
                    pa = make_uint4(h2u(__floats2half2_rn(f0.x, f0.y)),
                                    h2u(__floats2half2_rn(f0.z, f0.w)),
                                    h2u(__floats2half2_rn(f1.x, f1.y)),
                                    h2u(__floats2half2_rn(f1.z, f1.w)));
                    pb = make_uint4(h2u(__floats2half2_rn(f2.x, f2.y)),
                                    h2u(__floats2half2_rn(f2.z, f2.w)),
                                    h2u(__floats2half2_rn(f3.x, f3.y)),
                                    h2u(__floats2half2_rn(f3.z, f3.w)));
                } else {        // h chunk: already fp16 words
                    int widx = sbrow * (HID / 2) + (cn - 2) * 64 + sq * 8;
                    pa = *(const uint4*)&h_in[widx];
                    pb = *(const uint4*)&h_in[widx + 4];
                }
            }

            // ---- MMAs on chunk c: this warp's 2 k16-slices, 32x32 tile ----
            const uint32_t aoff = (uint32_t)(buf * ABUF_BYTES);
#pragma unroll
            for (int ksl = 0; ksl < 2; ++ksl) {
                const int ks = kg * 2 + ksl;                       // 0..7 in chunk
                const uint32_t woff = (uint32_t)((c * 8 + ks) * 32);
                uint32_t bw0[4], bw1[4];
                ldsm4(bw0, wlane0 + woff);   // n-frags 0,1 (cols wn*32+0..15)
                ldsm4(bw1, wlane1 + woff);   // n-frags 2,3 (cols wn*32+16..31)
#pragma unroll
                for (int mf = 0; mf < 2; ++mf) {
                    uint32_t a[4];
                    ldsm4(a, alane[mf] + aoff + (uint32_t)(ks * 32));
                    MMA_F16(d[mf][0], a, bw0[0], bw0[2]);
                    MMA_F16(d[mf][1], a, bw0[1], bw0[3]);
                    MMA_F16(d[mf][2], a, bw1[0], bw1[2]);
                    MMA_F16(d[mf][3], a, bw1[1], bw1[3]);
                }
            }

            // ---- commit prefetched chunk ----
            if (have_next) {
                int nb = buf ^ 1;
                *(uint4*)&Ab[nb * ABUF_WORDS + sdst]     = pa;
                *(uint4*)&Ab[nb * ABUF_WORDS + sdst + 4] = pb;
            }
            __syncthreads();
            buf ^= 1;
        }

        // ---- spill split-K partials to the four gate buffers ----
        {
            float* g = gates + kg * GT_WORDS;
            const int lq = lane >> 2, lr4 = lane & 3;
#pragma unroll
            for (int mf = 0; mf < 2; ++mf)
#pragma unroll
                for (int nf = 0; nf < 4; ++nf) {
                    int m = wm * 32 + mf * 16 + lq;
                    int n = wn * 32 + nf * 8 + lr4 * 2;
                    g[ m      * G_STRIDE + n    ] = d[mf][nf][0];
                    g[ m      * G_STRIDE + n + 1] = d[mf][nf][1];
                    g[(m + 8) * G_STRIDE + n    ] = d[mf][nf][2];
                    g[(m + 8) * G_STRIDE + n + 1] = d[mf][nf][3];
                }
        }
        __syncthreads();

        // ---- LSTM epilogue: sum 4 partials, c in regs, h stored fp16 ----
        {
            float hnew[2];
#pragma unroll
            for (int i = 0; i < 2; ++i) {
                int j = ej0 + i;
                float gi = bias_s[j],      gf = bias_s[16 + j];
                float gg = bias_s[32 + j], go = bias_s[48 + j];
#pragma unroll
                for (int p = 0; p < 4; ++p) {
                    const float* g = gates + p * GT_WORDS + eb * G_STRIDE;
                    gi += g[j];
                    gf += g[16 + j];
                    gg += g[32 + j];
                    go += g[48 + j];
                }
                float iv = fast_sigmoid(gi);
                float fv = fast_sigmoid(gf);
                float gv = fast_tanh(gg);
                float ov = fast_sigmoid(go);
                float cn = fv * creg[i] + iv * gv;
                creg[i] = cn;
                hnew[i] = ov * fast_tanh(cn);
            }
            h_out[hwi] = h2u(__floats2half2_rn(hnew[0], hnew[1]));
            if (t == T_STEPS - 1)
                *(float2*)&g_hf[(size_t)ebg * HID + jg0] =
                    make_float2(hnew[0], hnew[1]);
        }

        GROUP_ARRIVE();   // publish h; next step's x chunks hide the wait
    }

    GROUP_WAIT();         // final h published everywhere (for decode)

    // ---- decode by jTile==0 blocks from the fp32 h copy ----
    if (jTile == 0) {
        int b = bTile * BT + (tid >> 3);
        int part = tid & 7;
        const float* hb = g_hf + (size_t)b * HID + part * 64;
        const float* wd = W_dec + part * 64;
        float s = 0.f;
#pragma unroll 8
        for (int i = 0; i < 64; ++i) s = fmaf(hb[i], wd[i], s);
        s += __shfl_down_sync(0xFFFFFFFF, s, 4, 8);
        s += __shfl_down_sync(0xFFFFFFFF, s, 2, 8);
        s += __shfl_down_sync(0xFFFFFFFF, s, 1, 8);
        if (part == 0) out[b] = s + b_dec[0];
    }
#undef GROUP_ARRIVE
#undef GROUP_WAIT
}

extern "C" void kernel_launch(void* const* d_in, const int* in_sizes, int n_in,
                              void* d_out, int out_size)
{
    (void)in_sizes; (void)n_in; (void)out_size;
    const float* x     = (const float*)d_in[0];
    const float* h0    = (const float*)d_in[1];
    const float* c0    = (const float*)d_in[2];
    const float* W_ih  = (const float*)d_in[3];
    const float* W_hh  = (const float*)d_in[4];
    const float* b_ih  = (const float*)d_in[5];
    const float* b_hh  = (const float*)d_in[6];
    const float* W_dec = (const float*)d_in[7];
    const float* b_dec = (const float*)d_in[8];
    float* out = (float*)d_out;

    static bool attr_set = false;
    if (!attr_set) {
        cudaFuncSetAttribute(lstm_w16w_kernel,
                             cudaFuncAttributeMaxDynamicSharedMemorySize, SMEM_BYTES);
        attr_set = true;
    }

    dim3 grid(HID / JT, BATCH / BT);   // (32, 4) = 128 blocks, all co-resident
    lstm_w16w_kernel<<<grid, THREADS, SMEM_BYTES>>>(x, h0, c0, W_ih, W_hh,
                                                    b_ih, b_hh, W_dec, b_dec, out);
}